// round 12
// baseline (speedup 1.0000x reference)
#include <cuda_runtime.h>
#include <cuda_bf16.h>

#define B 512
#define D 768
#define MARGIN 1.0f
#define NTILES 36

// Scratch (allocation-free rule: __device__ globals)
__device__ float g_gramp[4][B * B];  // K-split partial Gram planes, mirrored
__device__ float g_gram[B * B];      // summed Gram (written by tile finishers)
__device__ float g_sqn[B];
__device__ unsigned int g_tile[NTILES];  // 4-way tickets; atomicInc(.,3) self-resets
__device__ double g_sum;
__device__ unsigned long long g_count;
__device__ unsigned int g_done;

// ---------------------------------------------------------------------------
// Kernel A: one wave of 148 blocks.
//   blocks 0..143  : upper-triangle Gram, 64x64 tiles, 4x4 micro-tile,
//                    K-split x4, pipelined loads, mirrored plane stores.
//                    The 4th (last) block of each tile sums the 4 planes out
//                    of L2 into g_gram (both mirrored regions, coalesced).
//   blocks 144..147: sq-norms (128 rows each); block 147 resets scalars
// ---------------------------------------------------------------------------
__global__ void gram_sqnorm_kernel(const float* __restrict__ X) {
    __shared__ float As[16][68];  // [k][row], padded
    __shared__ float Bs[16][68];
    __shared__ int fin;

    int bid = blockIdx.x;
    int tid = threadIdx.x;
    int lane = tid & 31, warp = tid >> 5;

    if (bid >= 144) {
        if (bid == 147 && tid == 0) {
            g_sum = 0.0;
            g_count = 0ull;
            g_done = 0u;
        }
        int rb = (bid - 144) * 128;
        #pragma unroll
        for (int i = 0; i < 16; i++) {
            int row = rb + warp * 16 + i;
            const float4* rp = (const float4*)(X + (size_t)row * D);
            float acc = 0.f;
            #pragma unroll
            for (int q = 0; q < 6; q++) {
                float4 v = rp[lane + 32 * q];
                acc += v.x * v.x + v.y * v.y + v.z * v.z + v.w * v.w;
            }
            #pragma unroll
            for (int o = 16; o; o >>= 1) acc += __shfl_down_sync(0xffffffffu, acc, o);
            if (lane == 0) g_sqn[row] = acc;
        }
        return;
    }

    int ks = bid & 3;             // k-slice 0..3
    int tile = bid >> 2;          // 0..35
    int idx = tile, by = 0;       // -> (by, bx), bx >= by, 8x8 grid
    for (;;) {
        int len = 8 - by;
        if (idx < len) break;
        idx -= len;
        by++;
    }
    int bx = by + idx;
    int rowBase = by * 64;
    int colBase = bx * 64;

    int tx = tid & 15, ty = tid >> 4;
    int lr = tid & 63;
    int lq = tid >> 6;

    const float* arow = X + (size_t)(rowBase + lr) * D + ks * 192 + lq * 4;
    const float* brow = X + (size_t)(colBase + lr) * D + ks * 192 + lq * 4;

    float acc[4][4];
    #pragma unroll
    for (int i = 0; i < 4; i++)
        #pragma unroll
        for (int j = 0; j < 4; j++) acc[i][j] = 0.f;

    float4 av = *(const float4*)arow;
    float4 bv = *(const float4*)brow;

    for (int kc = 0; kc < 192; kc += 16) {
        As[lq * 4 + 0][lr] = av.x; As[lq * 4 + 1][lr] = av.y;
        As[lq * 4 + 2][lr] = av.z; As[lq * 4 + 3][lr] = av.w;
        Bs[lq * 4 + 0][lr] = bv.x; Bs[lq * 4 + 1][lr] = bv.y;
        Bs[lq * 4 + 2][lr] = bv.z; Bs[lq * 4 + 3][lr] = bv.w;
        __syncthreads();
        if (kc + 16 < 192) {
            av = *(const float4*)(arow + kc + 16);
            bv = *(const float4*)(brow + kc + 16);
        }
        #pragma unroll
        for (int k = 0; k < 16; k++) {
            float4 a4 = *(const float4*)&As[k][ty * 4];
            float4 b4 = *(const float4*)&Bs[k][tx * 4];
            float a[4] = {a4.x, a4.y, a4.z, a4.w};
            float b[4] = {b4.x, b4.y, b4.z, b4.w};
            #pragma unroll
            for (int i = 0; i < 4; i++)
                #pragma unroll
                for (int j = 0; j < 4; j++) acc[i][j] += a[i] * b[j];
        }
        __syncthreads();
    }

    float* plane = g_gramp[ks];
    #pragma unroll
    for (int i = 0; i < 4; i++) {
        int r = rowBase + ty * 4 + i;
        *(float4*)&plane[r * B + colBase + tx * 4] =
            make_float4(acc[i][0], acc[i][1], acc[i][2], acc[i][3]);
    }
    if (bx != by) {
        #pragma unroll
        for (int j = 0; j < 4; j++) {
            int c = colBase + tx * 4 + j;
            *(float4*)&plane[c * B + rowBase + ty * 4] =
                make_float4(acc[0][j], acc[1][j], acc[2][j], acc[3][j]);
        }
    }

    // ---- tile ticket: 4th arriving k-slice block sums the planes ----
    __threadfence();
    __syncthreads();
    if (tid == 0) fin = (atomicInc(&g_tile[tile], 3u) == 3u);  // wraps 3->0
    __syncthreads();
    if (!fin) return;
    __threadfence();  // acquire: other slices' plane stores now visible

    // region 1: rows [rowBase,+64), cols [colBase,+64)
    #pragma unroll
    for (int i = 0; i < 4; i++) {
        int pos = tid + i * 256;         // 0..1023 float4 positions
        int r = rowBase + (pos >> 4);
        int c = colBase + (pos & 15) * 4;
        float4 s0 = *(const float4*)&g_gramp[0][r * B + c];
        float4 s1 = *(const float4*)&g_gramp[1][r * B + c];
        float4 s2 = *(const float4*)&g_gramp[2][r * B + c];
        float4 s3 = *(const float4*)&g_gramp[3][r * B + c];
        *(float4*)&g_gram[r * B + c] = make_float4(
            (s0.x + s1.x) + (s2.x + s3.x), (s0.y + s1.y) + (s2.y + s3.y),
            (s0.z + s1.z) + (s2.z + s3.z), (s0.w + s1.w) + (s2.w + s3.w));
    }
    if (bx != by) {
        // region 2 (mirror): rows [colBase,+64), cols [rowBase,+64)
        #pragma unroll
        for (int i = 0; i < 4; i++) {
            int pos = tid + i * 256;
            int r = colBase + (pos >> 4);
            int c = rowBase + (pos & 15) * 4;
            float4 s0 = *(const float4*)&g_gramp[0][r * B + c];
            float4 s1 = *(const float4*)&g_gramp[1][r * B + c];
            float4 s2 = *(const float4*)&g_gramp[2][r * B + c];
            float4 s3 = *(const float4*)&g_gramp[3][r * B + c];
            *(float4*)&g_gram[r * B + c] = make_float4(
                (s0.x + s1.x) + (s2.x + s3.x), (s0.y + s1.y) + (s2.y + s3.y),
                (s0.z + s1.z) + (s2.z + s3.z), (s0.w + s1.w) + (s2.w + s3.w));
        }
    }
}

// ---------------------------------------------------------------------------
// Kernel B: one block per anchor. 3-load prologue (float2 gram row, float2
// sqn, int2 types); ballot compaction; 4-positives-in-registers hinge loop.
// Last block finalizes.
// ---------------------------------------------------------------------------
__global__ void __launch_bounds__(256)
triplet_kernel(const int* __restrict__ types, float* __restrict__ out) {
    int a = blockIdx.x;
    __shared__ __align__(16) float posv[B + 4];
    __shared__ __align__(16) float negv[B + 4];
    __shared__ int cnt[2];
    __shared__ float ws[8];
    int tid = threadIdx.x;
    int lane = tid & 31, warp = tid >> 5;
    if (tid < 2) cnt[tid] = 0;

    // hoisted wide loads
    float2 g2 = ((const float2*)(g_gram + (size_t)a * B))[tid];
    float2 sq = ((const float2*)g_sqn)[tid];
    int2   tt = ((const int2*)types)[tid];
    int ta = types[a];
    float sa = g_sqn[a];

    int ja = 2 * tid, jb = 2 * tid + 1;
    float dva = (ja == a) ? 0.f : sqrtf(fmaxf(sa + sq.x - 2.f * g2.x, 0.f));
    float dvb = (jb == a) ? 0.f : sqrtf(fmaxf(sa + sq.y - 2.f * g2.y, 0.f));
    bool pa = (tt.x == ta);
    bool pb = (tt.y == ta);

    __syncthreads();  // cnt init visible

    unsigned lt_mask = (1u << lane) - 1u;
    {
        unsigned mp = __ballot_sync(0xffffffffu, pa);
        int cp = __popc(mp);
        int bp = 0, bn = 0;
        if (lane == 0) {
            bp = atomicAdd(&cnt[0], cp);
            bn = atomicAdd(&cnt[1], 32 - cp);
        }
        bp = __shfl_sync(0xffffffffu, bp, 0);
        bn = __shfl_sync(0xffffffffu, bn, 0);
        if (pa) posv[bp + __popc(mp & lt_mask)] = dva;
        else    negv[bn + __popc((~mp) & lt_mask)] = dva;
    }
    {
        unsigned mp = __ballot_sync(0xffffffffu, pb);
        int cp = __popc(mp);
        int bp = 0, bn = 0;
        if (lane == 0) {
            bp = atomicAdd(&cnt[0], cp);
            bn = atomicAdd(&cnt[1], 32 - cp);
        }
        bp = __shfl_sync(0xffffffffu, bp, 0);
        bn = __shfl_sync(0xffffffffu, bn, 0);
        if (pb) posv[bp + __popc(mp & lt_mask)] = dvb;
        else    negv[bn + __popc((~mp) & lt_mask)] = dvb;
    }
    __syncthreads();

    int np = cnt[0], nn = cnt[1];
    int nn4 = (nn + 3) & ~3;
    int np4 = (np + 3) & ~3;
    if (tid < nn4 - nn) negv[nn + tid] = 1e30f;   // pad: max(dp - INF, 0) = 0
    if (tid < np4 - np) posv[np + tid] = -1e30f;  // pad: max(-INF - dn, 0) = 0
    __syncthreads();

    const float4* negv4 = (const float4*)negv;
    int nq = nn4 >> 2;
    float a0 = 0.f, a1 = 0.f, a2 = 0.f, a3 = 0.f;
    for (int p = warp * 4; p < np4; p += 32) {  // 8 warps x 4 positives each
        float dp0 = posv[p + 0] + MARGIN;
        float dp1 = posv[p + 1] + MARGIN;
        float dp2 = posv[p + 2] + MARGIN;
        float dp3 = posv[p + 3] + MARGIN;
        for (int n = lane; n < nq; n += 32) {
            float4 v = negv4[n];
            a0 += fmaxf(dp0 - v.x, 0.f); a0 += fmaxf(dp0 - v.y, 0.f);
            a0 += fmaxf(dp0 - v.z, 0.f); a0 += fmaxf(dp0 - v.w, 0.f);
            a1 += fmaxf(dp1 - v.x, 0.f); a1 += fmaxf(dp1 - v.y, 0.f);
            a1 += fmaxf(dp1 - v.z, 0.f); a1 += fmaxf(dp1 - v.w, 0.f);
            a2 += fmaxf(dp2 - v.x, 0.f); a2 += fmaxf(dp2 - v.y, 0.f);
            a2 += fmaxf(dp2 - v.z, 0.f); a2 += fmaxf(dp2 - v.w, 0.f);
            a3 += fmaxf(dp3 - v.x, 0.f); a3 += fmaxf(dp3 - v.y, 0.f);
            a3 += fmaxf(dp3 - v.z, 0.f); a3 += fmaxf(dp3 - v.w, 0.f);
        }
    }
    float acc = (a0 + a1) + (a2 + a3);

    #pragma unroll
    for (int o = 16; o; o >>= 1) acc += __shfl_down_sync(0xffffffffu, acc, o);
    if (lane == 0) ws[warp] = acc;
    __syncthreads();
    if (tid == 0) {
        float s = 0.f;
        #pragma unroll
        for (int w = 0; w < 8; w++) s += ws[w];
        atomicAdd(&g_sum, (double)s);
        atomicAdd(&g_count, (unsigned long long)((long long)np * nn));
        __threadfence();
        unsigned d = atomicInc(&g_done, 0xffffffffu);
        if (d == B - 1) {
            double S = atomicAdd(&g_sum, 0.0);
            unsigned long long C = atomicAdd(&g_count, 0ull);
            double V = (double)C;
            double b3 = 134217728.0;  // 512^3
            out[0] = (float)(((b3 - V) * (double)MARGIN + S) / V);
        }
    }
}

extern "C" void kernel_launch(void* const* d_in, const int* in_sizes, int n_in,
                              void* d_out, int out_size) {
    int ti = 0, ei = 1;
    if (in_sizes[0] == B * D) { ti = 1; ei = 0; }
    const int* types = (const int*)d_in[ti];
    const float* X = (const float*)d_in[ei];
    float* out = (float*)d_out;

    gram_sqnorm_kernel<<<148, 256>>>(X);
    triplet_kernel<<<B, 256>>>(types, out);
}

// round 13
// speedup vs baseline: 1.1771x; 1.1771x over previous
#include <cuda_runtime.h>
#include <cuda_bf16.h>

#define B 512
#define D 768
#define MARGIN 1.0f

// Scratch (allocation-free rule: __device__ globals)
__device__ float g_gramp[4][B * B];  // K-split partial Gram planes, mirrored
__device__ float g_sqn[B];
__device__ double g_sum;
__device__ unsigned long long g_count;
__device__ unsigned int g_done;

// ---------------------------------------------------------------------------
// Kernel A (round-11 proven version, reverted): one wave of 148 blocks.
//   blocks 0..143  : upper-triangle Gram, 64x64 tiles, 4x4 micro-tile,
//                    K-split x4, pipelined global loads, mirrored plane stores
//   blocks 144..147: sq-norms (128 rows each); block 147 resets scalars
// ---------------------------------------------------------------------------
__global__ void gram_sqnorm_kernel(const float* __restrict__ X) {
    __shared__ float As[16][68];  // [k][row], padded
    __shared__ float Bs[16][68];

    int bid = blockIdx.x;
    int tid = threadIdx.x;
    int lane = tid & 31, warp = tid >> 5;

    if (bid >= 144) {
        if (bid == 147 && tid == 0) {
            g_sum = 0.0;
            g_count = 0ull;
            g_done = 0u;
        }
        int rb = (bid - 144) * 128;
        #pragma unroll
        for (int i = 0; i < 16; i++) {
            int row = rb + warp * 16 + i;
            const float4* rp = (const float4*)(X + (size_t)row * D);
            float acc = 0.f;
            #pragma unroll
            for (int q = 0; q < 6; q++) {
                float4 v = rp[lane + 32 * q];
                acc += v.x * v.x + v.y * v.y + v.z * v.z + v.w * v.w;
            }
            #pragma unroll
            for (int o = 16; o; o >>= 1) acc += __shfl_down_sync(0xffffffffu, acc, o);
            if (lane == 0) g_sqn[row] = acc;
        }
        return;
    }

    int ks = bid & 3;            // k-slice 0..3
    int idx = bid >> 2, by = 0;  // tile 0..35 -> (by, bx), bx >= by, 8x8 grid
    for (;;) {
        int len = 8 - by;
        if (idx < len) break;
        idx -= len;
        by++;
    }
    int bx = by + idx;
    int rowBase = by * 64;
    int colBase = bx * 64;

    int tx = tid & 15, ty = tid >> 4;
    int lr = tid & 63;
    int lq = tid >> 6;

    const float* arow = X + (size_t)(rowBase + lr) * D + ks * 192 + lq * 4;
    const float* brow = X + (size_t)(colBase + lr) * D + ks * 192 + lq * 4;

    float acc[4][4];
    #pragma unroll
    for (int i = 0; i < 4; i++)
        #pragma unroll
        for (int j = 0; j < 4; j++) acc[i][j] = 0.f;

    float4 av = *(const float4*)arow;
    float4 bv = *(const float4*)brow;

    for (int kc = 0; kc < 192; kc += 16) {
        As[lq * 4 + 0][lr] = av.x; As[lq * 4 + 1][lr] = av.y;
        As[lq * 4 + 2][lr] = av.z; As[lq * 4 + 3][lr] = av.w;
        Bs[lq * 4 + 0][lr] = bv.x; Bs[lq * 4 + 1][lr] = bv.y;
        Bs[lq * 4 + 2][lr] = bv.z; Bs[lq * 4 + 3][lr] = bv.w;
        __syncthreads();
        if (kc + 16 < 192) {
            av = *(const float4*)(arow + kc + 16);
            bv = *(const float4*)(brow + kc + 16);
        }
        #pragma unroll
        for (int k = 0; k < 16; k++) {
            float4 a4 = *(const float4*)&As[k][ty * 4];
            float4 b4 = *(const float4*)&Bs[k][tx * 4];
            float a[4] = {a4.x, a4.y, a4.z, a4.w};
            float b[4] = {b4.x, b4.y, b4.z, b4.w};
            #pragma unroll
            for (int i = 0; i < 4; i++)
                #pragma unroll
                for (int j = 0; j < 4; j++) acc[i][j] += a[i] * b[j];
        }
        __syncthreads();
    }

    float* plane = g_gramp[ks];
    #pragma unroll
    for (int i = 0; i < 4; i++) {
        int r = rowBase + ty * 4 + i;
        *(float4*)&plane[r * B + colBase + tx * 4] =
            make_float4(acc[i][0], acc[i][1], acc[i][2], acc[i][3]);
    }
    if (bx != by) {
        #pragma unroll
        for (int j = 0; j < 4; j++) {
            int c = colBase + tx * 4 + j;
            *(float4*)&plane[c * B + rowBase + ty * 4] =
                make_float4(acc[0][j], acc[1][j], acc[2][j], acc[3][j]);
        }
    }
}

// ---------------------------------------------------------------------------
// Kernel B: grid = 256, TWO anchors per block (bid, bid+256). One hoisted
// memory window serves both anchors (sqn/types shared; two gram rows).
// Both compactions into separate smem arrays, both hinges into the same
// accumulators -> one reduction + one atomic pair per 2 anchors.
// ---------------------------------------------------------------------------
__device__ __forceinline__ void compact_pass(bool isPos, float dv,
                                             float* posv, float* negv,
                                             int* cntP, int* cntN,
                                             int lane, unsigned lt_mask) {
    unsigned mp = __ballot_sync(0xffffffffu, isPos);
    int cp = __popc(mp);
    int bp = 0, bn = 0;
    if (lane == 0) {
        bp = atomicAdd(cntP, cp);
        bn = atomicAdd(cntN, 32 - cp);
    }
    bp = __shfl_sync(0xffffffffu, bp, 0);
    bn = __shfl_sync(0xffffffffu, bn, 0);
    if (isPos) posv[bp + __popc(mp & lt_mask)] = dv;
    else       negv[bn + __popc((~mp) & lt_mask)] = dv;
}

__global__ void __launch_bounds__(256)
triplet_kernel(const int* __restrict__ types, float* __restrict__ out) {
    __shared__ __align__(16) float posv[2][B + 4];
    __shared__ __align__(16) float negv[2][B + 4];
    __shared__ int cnt[4];
    __shared__ float ws[8];
    int tid = threadIdx.x;
    int lane = tid & 31, warp = tid >> 5;
    if (tid < 4) cnt[tid] = 0;

    int a0 = blockIdx.x;
    int a1 = blockIdx.x + 256;

    // ---- single hoisted memory window for both anchors ----
    const float2* q0 = (const float2*)&g_gramp[0][a0 * B];
    const float2* q1 = (const float2*)&g_gramp[1][a0 * B];
    const float2* q2 = (const float2*)&g_gramp[2][a0 * B];
    const float2* q3 = (const float2*)&g_gramp[3][a0 * B];
    const float2* r0 = (const float2*)&g_gramp[0][a1 * B];
    const float2* r1 = (const float2*)&g_gramp[1][a1 * B];
    const float2* r2 = (const float2*)&g_gramp[2][a1 * B];
    const float2* r3 = (const float2*)&g_gramp[3][a1 * B];
    float2 u0 = q0[tid], u1 = q1[tid], u2 = q2[tid], u3 = q3[tid];
    float2 w0 = r0[tid], w1 = r1[tid], w2 = r2[tid], w3 = r3[tid];
    float2 sq = ((const float2*)g_sqn)[tid];
    int2   tt = ((const int2*)types)[tid];
    int ta0 = types[a0], ta1 = types[a1];
    float sa0 = g_sqn[a0], sa1 = g_sqn[a1];

    int ja = 2 * tid, jb = 2 * tid + 1;
    float g0a = (u0.x + u1.x) + (u2.x + u3.x);
    float g0b = (u0.y + u1.y) + (u2.y + u3.y);
    float g1a = (w0.x + w1.x) + (w2.x + w3.x);
    float g1b = (w0.y + w1.y) + (w2.y + w3.y);
    float dv0a = (ja == a0) ? 0.f : sqrtf(fmaxf(sa0 + sq.x - 2.f * g0a, 0.f));
    float dv0b = (jb == a0) ? 0.f : sqrtf(fmaxf(sa0 + sq.y - 2.f * g0b, 0.f));
    float dv1a = (ja == a1) ? 0.f : sqrtf(fmaxf(sa1 + sq.x - 2.f * g1a, 0.f));
    float dv1b = (jb == a1) ? 0.f : sqrtf(fmaxf(sa1 + sq.y - 2.f * g1b, 0.f));

    __syncthreads();  // cnt init visible

    unsigned lt_mask = (1u << lane) - 1u;
    compact_pass(tt.x == ta0, dv0a, posv[0], negv[0], &cnt[0], &cnt[1], lane, lt_mask);
    compact_pass(tt.y == ta0, dv0b, posv[0], negv[0], &cnt[0], &cnt[1], lane, lt_mask);
    compact_pass(tt.x == ta1, dv1a, posv[1], negv[1], &cnt[2], &cnt[3], lane, lt_mask);
    compact_pass(tt.y == ta1, dv1b, posv[1], negv[1], &cnt[2], &cnt[3], lane, lt_mask);
    __syncthreads();

    int np0 = cnt[0], nn0 = cnt[1];
    int np1 = cnt[2], nn1 = cnt[3];
    int nn0p = (nn0 + 3) & ~3, np0p = (np0 + 3) & ~3;
    int nn1p = (nn1 + 3) & ~3, np1p = (np1 + 3) & ~3;
    if (tid < nn0p - nn0) negv[0][nn0 + tid] = 1e30f;   // pad -> 0 contribution
    if (tid < np0p - np0) posv[0][np0 + tid] = -1e30f;
    if (tid < nn1p - nn1) negv[1][nn1 + tid] = 1e30f;
    if (tid < np1p - np1) posv[1][np1 + tid] = -1e30f;
    __syncthreads();

    float a0r = 0.f, a1r = 0.f, a2r = 0.f, a3r = 0.f;
    #pragma unroll
    for (int side = 0; side < 2; side++) {
        const float* pv = posv[side];
        const float4* nv4 = (const float4*)negv[side];
        int npp = side ? np1p : np0p;
        int nq  = (side ? nn1p : nn0p) >> 2;
        for (int p = warp * 4; p < npp; p += 32) {
            float dp0 = pv[p + 0] + MARGIN;
            float dp1 = pv[p + 1] + MARGIN;
            float dp2 = pv[p + 2] + MARGIN;
            float dp3 = pv[p + 3] + MARGIN;
            for (int n = lane; n < nq; n += 32) {
                float4 v = nv4[n];
                a0r += fmaxf(dp0 - v.x, 0.f); a0r += fmaxf(dp0 - v.y, 0.f);
                a0r += fmaxf(dp0 - v.z, 0.f); a0r += fmaxf(dp0 - v.w, 0.f);
                a1r += fmaxf(dp1 - v.x, 0.f); a1r += fmaxf(dp1 - v.y, 0.f);
                a1r += fmaxf(dp1 - v.z, 0.f); a1r += fmaxf(dp1 - v.w, 0.f);
                a2r += fmaxf(dp2 - v.x, 0.f); a2r += fmaxf(dp2 - v.y, 0.f);
                a2r += fmaxf(dp2 - v.z, 0.f); a2r += fmaxf(dp2 - v.w, 0.f);
                a3r += fmaxf(dp3 - v.x, 0.f); a3r += fmaxf(dp3 - v.y, 0.f);
                a3r += fmaxf(dp3 - v.z, 0.f); a3r += fmaxf(dp3 - v.w, 0.f);
            }
        }
    }
    float acc = (a0r + a1r) + (a2r + a3r);

    #pragma unroll
    for (int o = 16; o; o >>= 1) acc += __shfl_down_sync(0xffffffffu, acc, o);
    if (lane == 0) ws[warp] = acc;
    __syncthreads();
    if (tid == 0) {
        float s = 0.f;
        #pragma unroll
        for (int w = 0; w < 8; w++) s += ws[w];
        atomicAdd(&g_sum, (double)s);
        atomicAdd(&g_count, (unsigned long long)((long long)np0 * nn0 +
                                                 (long long)np1 * nn1));
        __threadfence();
        unsigned d = atomicInc(&g_done, 0xffffffffu);
        if (d == 255u) {
            double S = atomicAdd(&g_sum, 0.0);
            unsigned long long C = atomicAdd(&g_count, 0ull);
            double V = (double)C;
            double b3 = 134217728.0;  // 512^3
            out[0] = (float)(((b3 - V) * (double)MARGIN + S) / V);
        }
    }
}

extern "C" void kernel_launch(void* const* d_in, const int* in_sizes, int n_in,
                              void* d_out, int out_size) {
    int ti = 0, ei = 1;
    if (in_sizes[0] == B * D) { ti = 1; ei = 0; }
    const int* types = (const int*)d_in[ti];
    const float* X = (const float*)d_in[ei];
    float* out = (float*)d_out;

    gram_sqnorm_kernel<<<148, 256>>>(X);
    triplet_kernel<<<256, 256>>>(types, out);
}